// round 1
// baseline (speedup 1.0000x reference)
#include <cuda_runtime.h>
#include <cuda_bf16.h>
#include <math.h>
#include <stdint.h>

// Problem constants
#define BQ   2
#define TSEQ 2048
#define DMODEL 2048
#define NH   16
#define NKV  8
#define DH   128
#define GRP  2            // NH / NKV
#define MROWS (BQ*TSEQ)   // 4096

// ---------------- device scratch (allocation-free rule: __device__ globals) ----
__device__ float g_qkv[MROWS * 4096];         // [4096, 4096]: q(2048) | k(1024) | v(1024)
__device__ float g_q  [BQ * NH  * TSEQ * DH]; // [B,H,T,Dh]
__device__ float g_k  [BQ * NKV * TSEQ * DH]; // [B,Hkv,T,Dh]
__device__ float g_v  [BQ * NKV * TSEQ * DH];
__device__ float g_ctx[MROWS * DMODEL];       // [B,T,H*Dh]
__device__ float g_cos[TSEQ * 64];
__device__ float g_sin[TSEQ * 64];

// ---------------- RoPE table (double-precision angles, f32 trig) --------------
__global__ void build_rope_kernel() {
    int t = blockIdx.x;
    int i = threadIdx.x;  // 0..63
    double inv = exp(-((double)(2 * i) / 128.0) * log(1.0e6));
    double ang = (double)t * inv;
    float af = (float)ang;
    g_cos[t * 64 + i] = cosf(af);
    g_sin[t * 64 + i] = sinf(af);
}

// ---------------- SGEMM: C[m, coff+n] = A[M,K] @ B[N,K]^T ---------------------
// 128x128 tile, BK=8, 256 threads, 8x8 per-thread fragment.
__global__ __launch_bounds__(256) void sgemm_kernel(
    const float* __restrict__ A, const float* __restrict__ Bw,
    float* __restrict__ C, int K, int ldc, int coff)
{
    __shared__ float As[8][128];
    __shared__ float Bs[8][128];

    const int tid = threadIdx.x;
    const int tx = tid & 15;
    const int ty = tid >> 4;
    const int m0 = blockIdx.y * 128;
    const int n0 = blockIdx.x * 128;

    const int lrow = tid >> 1;        // 0..127
    const int lseg = (tid & 1) * 4;   // 0 or 4

    const float* Aptr = A + (size_t)(m0 + lrow) * K + lseg;
    const float* Bptr = Bw + (size_t)(n0 + lrow) * K + lseg;

    float acc[8][8];
    #pragma unroll
    for (int i = 0; i < 8; i++)
        #pragma unroll
        for (int j = 0; j < 8; j++) acc[i][j] = 0.f;

    for (int k0 = 0; k0 < K; k0 += 8) {
        float4 av = *(const float4*)(Aptr + k0);
        float4 bv = *(const float4*)(Bptr + k0);
        __syncthreads();
        As[lseg + 0][lrow] = av.x; As[lseg + 1][lrow] = av.y;
        As[lseg + 2][lrow] = av.z; As[lseg + 3][lrow] = av.w;
        Bs[lseg + 0][lrow] = bv.x; Bs[lseg + 1][lrow] = bv.y;
        Bs[lseg + 2][lrow] = bv.z; Bs[lseg + 3][lrow] = bv.w;
        __syncthreads();
        #pragma unroll
        for (int kk = 0; kk < 8; kk++) {
            float4 a0 = *(const float4*)&As[kk][ty * 8];
            float4 a1 = *(const float4*)&As[kk][ty * 8 + 4];
            float4 b0 = *(const float4*)&Bs[kk][tx * 8];
            float4 b1 = *(const float4*)&Bs[kk][tx * 8 + 4];
            float a[8] = {a0.x, a0.y, a0.z, a0.w, a1.x, a1.y, a1.z, a1.w};
            float b[8] = {b0.x, b0.y, b0.z, b0.w, b1.x, b1.y, b1.z, b1.w};
            #pragma unroll
            for (int i = 0; i < 8; i++)
                #pragma unroll
                for (int j = 0; j < 8; j++)
                    acc[i][j] = fmaf(a[i], b[j], acc[i][j]);
        }
    }

    #pragma unroll
    for (int i = 0; i < 8; i++) {
        float* crow = C + (size_t)(m0 + ty * 8 + i) * ldc + coff + n0 + tx * 8;
        #pragma unroll
        for (int j = 0; j < 8; j++) crow[j] = acc[i][j];
    }
}

// ---------------- RMSNorm + RoPE + scatter to [B,H,T,Dh] ----------------------
// grid (B*T, NH + 2*NKV), block 128
__global__ __launch_bounds__(128) void qkv_postprocess_kernel(
    const float* __restrict__ qnw, const float* __restrict__ knw)
{
    const int tg = blockIdx.x;            // b*T + t
    const int b = tg / TSEQ;
    const int t = tg - b * TSEQ;
    const int hh = blockIdx.y;
    const int d = threadIdx.x;

    const float* src;
    float* dst;
    const float* w = qnw;
    bool rope = true;
    if (hh < NH) {
        src = g_qkv + (size_t)tg * 4096 + hh * DH;
        dst = g_q + ((size_t)(b * NH + hh) * TSEQ + t) * DH;
    } else if (hh < NH + NKV) {
        int h = hh - NH;
        src = g_qkv + (size_t)tg * 4096 + 2048 + h * DH;
        w = knw;
        dst = g_k + ((size_t)(b * NKV + h) * TSEQ + t) * DH;
    } else {
        int h = hh - NH - NKV;
        src = g_qkv + (size_t)tg * 4096 + 3072 + h * DH;
        dst = g_v + ((size_t)(b * NKV + h) * TSEQ + t) * DH;
        rope = false;
    }

    float x = src[d];
    if (!rope) { dst[d] = x; return; }

    // RMSNorm over 128 dims
    float ss = x * x;
    #pragma unroll
    for (int o = 16; o > 0; o >>= 1) ss += __shfl_xor_sync(0xffffffffu, ss, o);
    __shared__ float red[4];
    if ((d & 31) == 0) red[d >> 5] = ss;
    __syncthreads();
    float total = red[0] + red[1] + red[2] + red[3];
    float rms = rsqrtf(total * (1.0f / 128.0f) + 1e-6f);
    float nx = x * rms * w[d];

    __shared__ float sh[128];
    sh[d] = nx;
    __syncthreads();
    float rot = (d < 64) ? -sh[d + 64] : sh[d - 64];
    int i = d & 63;
    float c = g_cos[t * 64 + i];
    float s = g_sin[t * 64 + i];
    dst[d] = nx * c + rot * s;
}

// ---------------- Flash attention (causal, GQA) -------------------------------
// grid (T/64, B*NH), 256 threads. BM=64 queries, BN=64 keys.
// smem floats: Qs 64*128=8192 | KVs 64*129=8256 | Ss 64*65=4160 | m,l,al 3*64
#define FLASH_SMEM_FLOATS (8192 + 8256 + 4160 + 192)

__global__ __launch_bounds__(256) void flash_attn_kernel() {
    extern __shared__ float sm[];
    float* Qs  = sm;
    float* KVs = sm + 8192;
    float* Ss  = sm + 16448;
    float* m_s = sm + 20608;
    float* l_s = sm + 20672;
    float* al_s = sm + 20736;

    const int tid = threadIdx.x;
    const int tx = tid & 15;
    const int ty = tid >> 4;
    const int bh = blockIdx.y;
    const int b = bh >> 4;
    const int h = bh & 15;
    const int hk = h >> 1;   // GQA group of 2
    const int q0 = blockIdx.x * 64;

    const float* Qbase = g_q + ((size_t)(b * NH + h) * TSEQ + q0) * DH;
    const float* Kbase = g_k + (size_t)(b * NKV + hk) * TSEQ * DH;
    const float* Vbase = g_v + (size_t)(b * NKV + hk) * TSEQ * DH;

    // load Q tile (stays resident)
    for (int idx = tid; idx < 64 * 32; idx += 256) {
        int r = idx >> 5, c = (idx & 31) << 2;
        *(float4*)(Qs + r * 128 + c) = *(const float4*)(Qbase + r * 128 + c);
    }
    if (tid < 64) { m_s[tid] = -INFINITY; l_s[tid] = 0.f; }

    float acc[4][8];
    #pragma unroll
    for (int i = 0; i < 4; i++)
        #pragma unroll
        for (int j = 0; j < 8; j++) acc[i][j] = 0.f;

    __syncthreads();

    const float scale = 0.08838834764831845f;  // 1/sqrt(128)

    for (int k0 = 0; k0 <= q0; k0 += 64) {
        // load K tile (stride 129 to dodge bank conflicts on K reads)
        for (int idx = tid; idx < 64 * 32; idx += 256) {
            int r = idx >> 5, c = (idx & 31) << 2;
            float4 v = *(const float4*)(Kbase + (size_t)(k0 + r) * 128 + c);
            float* dstp = KVs + r * 129 + c;
            dstp[0] = v.x; dstp[1] = v.y; dstp[2] = v.z; dstp[3] = v.w;
        }
        __syncthreads();

        // S = Q @ K^T (each thread 4x4 of 64x64)
        float sacc[4][4];
        #pragma unroll
        for (int i = 0; i < 4; i++)
            #pragma unroll
            for (int j = 0; j < 4; j++) sacc[i][j] = 0.f;

        #pragma unroll 4
        for (int d = 0; d < 128; d++) {
            float a[4], bb[4];
            #pragma unroll
            for (int i = 0; i < 4; i++) a[i] = Qs[(ty * 4 + i) * 128 + d];
            #pragma unroll
            for (int j = 0; j < 4; j++) bb[j] = KVs[(tx * 4 + j) * 129 + d];
            #pragma unroll
            for (int i = 0; i < 4; i++)
                #pragma unroll
                for (int j = 0; j < 4; j++)
                    sacc[i][j] = fmaf(a[i], bb[j], sacc[i][j]);
        }

        const bool diag = (k0 == q0);
        #pragma unroll
        for (int i = 0; i < 4; i++)
            #pragma unroll
            for (int j = 0; j < 4; j++) {
                float v = sacc[i][j] * scale;
                if (diag && (tx * 4 + j) > (ty * 4 + i)) v = -INFINITY;
                Ss[(ty * 4 + i) * 65 + tx * 4 + j] = v;
            }
        __syncthreads();

        // softmax (64 threads) overlapped with V tile load (192 threads)
        if (tid < 64) {
            const int r = tid;
            float mo = m_s[r];
            float mx = mo;
            #pragma unroll 8
            for (int j = 0; j < 64; j++) mx = fmaxf(mx, Ss[r * 65 + j]);
            float al = __expf(mo - mx);
            float lsum = 0.f;
            #pragma unroll 8
            for (int j = 0; j < 64; j++) {
                float p = __expf(Ss[r * 65 + j] - mx);
                Ss[r * 65 + j] = p;
                lsum += p;
            }
            m_s[r] = mx;
            l_s[r] = l_s[r] * al + lsum;
            al_s[r] = al;
        } else {
            for (int idx = tid - 64; idx < 64 * 32; idx += 192) {
                int r = idx >> 5, c = (idx & 31) << 2;
                float4 v = *(const float4*)(Vbase + (size_t)(k0 + r) * 128 + c);
                float* dstp = KVs + r * 129 + c;
                dstp[0] = v.x; dstp[1] = v.y; dstp[2] = v.z; dstp[3] = v.w;
            }
        }
        __syncthreads();

        // rescale + acc += P @ V (each thread rows ty*4..+3, cols tx*8..+7)
        float al[4];
        #pragma unroll
        for (int i = 0; i < 4; i++) al[i] = al_s[ty * 4 + i];
        #pragma unroll
        for (int i = 0; i < 4; i++)
            #pragma unroll
            for (int j = 0; j < 8; j++) acc[i][j] *= al[i];

        #pragma unroll 2
        for (int kk = 0; kk < 64; kk++) {
            float p[4], vv[8];
            #pragma unroll
            for (int i = 0; i < 4; i++) p[i] = Ss[(ty * 4 + i) * 65 + kk];
            #pragma unroll
            for (int j = 0; j < 8; j++) vv[j] = KVs[kk * 129 + tx * 8 + j];
            #pragma unroll
            for (int i = 0; i < 4; i++)
                #pragma unroll
                for (int j = 0; j < 8; j++)
                    acc[i][j] = fmaf(p[i], vv[j], acc[i][j]);
        }
        __syncthreads();
    }

    // epilogue: normalize, write ctx as [B,T,H*Dh]
    #pragma unroll
    for (int i = 0; i < 4; i++) {
        float invl = 1.0f / l_s[ty * 4 + i];
        float* orow = g_ctx + (((size_t)b * TSEQ + q0 + ty * 4 + i) * NH + h) * DH + tx * 8;
        #pragma unroll
        for (int j = 0; j < 8; j++) orow[j] = acc[i][j] * invl;
    }
}

// ---------------- launch ------------------------------------------------------
extern "C" void kernel_launch(void* const* d_in, const int* in_sizes, int n_in,
                              void* d_out, int out_size) {
    const float* x   = (const float*)d_in[0];
    const float* wq  = (const float*)d_in[1];
    const float* wk  = (const float*)d_in[2];
    const float* wv  = (const float*)d_in[3];
    const float* wo  = (const float*)d_in[4];
    const float* qnw = (const float*)d_in[5];
    const float* knw = (const float*)d_in[6];
    float* out = (float*)d_out;

    float *qkv_p, *ctx_p;
    cudaGetSymbolAddress((void**)&qkv_p, g_qkv);
    cudaGetSymbolAddress((void**)&ctx_p, g_ctx);

    // RoPE table (cheap, rebuilt every call for determinism)
    build_rope_kernel<<<TSEQ, 64>>>();

    // QKV projections into g_qkv [4096, 4096]
    sgemm_kernel<<<dim3(2048 / 128, MROWS / 128), 256>>>(x, wq, qkv_p, DMODEL, 4096, 0);
    sgemm_kernel<<<dim3(1024 / 128, MROWS / 128), 256>>>(x, wk, qkv_p, DMODEL, 4096, 2048);
    sgemm_kernel<<<dim3(1024 / 128, MROWS / 128), 256>>>(x, wv, qkv_p, DMODEL, 4096, 3072);

    // RMSNorm + RoPE + layout change
    qkv_postprocess_kernel<<<dim3(MROWS, NH + 2 * NKV), 128>>>(qnw, knw);

    // Flash attention
    cudaFuncSetAttribute(flash_attn_kernel,
                         cudaFuncAttributeMaxDynamicSharedMemorySize,
                         FLASH_SMEM_FLOATS * 4);
    flash_attn_kernel<<<dim3(TSEQ / 64, BQ * NH), 256, FLASH_SMEM_FLOATS * 4>>>();

    // Output projection
    sgemm_kernel<<<dim3(2048 / 128, MROWS / 128), 256>>>(ctx_p, wo, out, DMODEL, DMODEL, 0);
}

// round 3
// speedup vs baseline: 2.6417x; 2.6417x over previous
#include <cuda_runtime.h>
#include <cuda_bf16.h>
#include <math.h>
#include <stdint.h>

// Problem constants
#define BQ   2
#define TSEQ 2048
#define DMODEL 2048
#define NH   16
#define NKV  8
#define DH   128
#define MROWS (BQ*TSEQ)   // 4096

// ---------------- device scratch ----------------------------------------------
__device__ float g_qkv[MROWS * 4096];         // q(2048) | k(1024) | v(1024)
__device__ float g_q  [BQ * NH  * TSEQ * DH];
__device__ float g_k  [BQ * NKV * TSEQ * DH];
__device__ float g_v  [BQ * NKV * TSEQ * DH];
__device__ float g_ctx[MROWS * DMODEL];
__device__ float g_cos[TSEQ * 64];
__device__ float g_sin[TSEQ * 64];

// ---------------- helpers -----------------------------------------------------
__device__ __forceinline__ uint32_t f2tf32(float f) {
    uint32_t u;
    asm("cvt.rna.tf32.f32 %0, %1;" : "=r"(u) : "f"(f));
    return u;
}
__device__ __forceinline__ uint4 cvt4(float4 v) {
    uint4 u;
    u.x = f2tf32(v.x); u.y = f2tf32(v.y); u.z = f2tf32(v.z); u.w = f2tf32(v.w);
    return u;
}
__device__ __forceinline__ uint4 cvt4s(float4 v, float s) {
    uint4 u;
    u.x = f2tf32(v.x * s); u.y = f2tf32(v.y * s);
    u.z = f2tf32(v.z * s); u.w = f2tf32(v.w * s);
    return u;
}
// D += A(m16k8 row) * B(k8n8 col), tf32
__device__ __forceinline__ void mma8(float* d, const uint32_t* a, const uint32_t* b) {
    asm volatile(
        "mma.sync.aligned.m16n8k8.row.col.f32.tf32.tf32.f32 "
        "{%0,%1,%2,%3}, {%4,%5,%6,%7}, {%8,%9}, {%0,%1,%2,%3};"
        : "+f"(d[0]), "+f"(d[1]), "+f"(d[2]), "+f"(d[3])
        : "r"(a[0]), "r"(a[1]), "r"(a[2]), "r"(a[3]), "r"(b[0]), "r"(b[1]));
}

// ---------------- RoPE table --------------------------------------------------
__global__ void build_rope_kernel() {
    int t = blockIdx.x;
    int i = threadIdx.x;  // 0..63
    double inv = exp(-((double)(2 * i) / 128.0) * log(1.0e6));
    float af = (float)((double)t * inv);
    g_cos[t * 64 + i] = cosf(af);
    g_sin[t * 64 + i] = sinf(af);
}

// ---------------- TF32 mma.sync GEMM: C[m, coff+n] = A[M,K] @ B[N,K]^T --------
// 128x128 tile, BK=16, 256 threads (8 warps), warp tile 32x64.
#define LDAB 20  // smem row pitch (floats): (20*m + k) mod 32 bijective on 8x4

__global__ __launch_bounds__(256, 2) void tf32gemm_kernel(
    const float* __restrict__ A, const float* __restrict__ Bw,
    float* __restrict__ C, int K, int ldc, int coff)
{
    __shared__ uint32_t As[128 * LDAB];
    __shared__ uint32_t Bs[128 * LDAB];

    const int tid  = threadIdx.x;
    const int lane = tid & 31;
    const int wid  = tid >> 5;
    const int gid  = lane >> 2;
    const int tig  = lane & 3;
    const int wm   = (wid & 3) * 32;   // 4 warps over m
    const int wn   = (wid >> 2) * 64;  // 2 warps over n
    const int m0 = blockIdx.y * 128;
    const int n0 = blockIdx.x * 128;

    const int row  = tid >> 1;           // 0..127
    const int kseg = (tid & 1) * 8;      // 0 or 8
    const float* Aptr = A  + (size_t)(m0 + row) * K + kseg;
    const float* Bptr = Bw + (size_t)(n0 + row) * K + kseg;
    const int sts = row * LDAB + kseg;

    float acc[2][8][4];
    #pragma unroll
    for (int mt = 0; mt < 2; mt++)
        #pragma unroll
        for (int nt = 0; nt < 8; nt++)
            #pragma unroll
            for (int r = 0; r < 4; r++) acc[mt][nt][r] = 0.f;

    float4 pa0 = *(const float4*)(Aptr);
    float4 pa1 = *(const float4*)(Aptr + 4);
    float4 pb0 = *(const float4*)(Bptr);
    float4 pb1 = *(const float4*)(Bptr + 4);

    const int niter = K >> 4;
    for (int kt = 0; kt < niter; kt++) {
        __syncthreads();
        *(uint4*)&As[sts]     = cvt4(pa0);
        *(uint4*)&As[sts + 4] = cvt4(pa1);
        *(uint4*)&Bs[sts]     = cvt4(pb0);
        *(uint4*)&Bs[sts + 4] = cvt4(pb1);
        __syncthreads();
        if (kt + 1 < niter) {
            const float* ap = Aptr + (kt + 1) * 16;
            const float* bp = Bptr + (kt + 1) * 16;
            pa0 = *(const float4*)(ap);
            pa1 = *(const float4*)(ap + 4);
            pb0 = *(const float4*)(bp);
            pb1 = *(const float4*)(bp + 4);
        }
        #pragma unroll
        for (int ks = 0; ks < 16; ks += 8) {
            uint32_t af[2][4], bf[8][2];
            #pragma unroll
            for (int mt = 0; mt < 2; mt++) {
                int base = (wm + mt * 16 + gid) * LDAB + ks + tig;
                af[mt][0] = As[base];
                af[mt][1] = As[base + 8 * LDAB];
                af[mt][2] = As[base + 4];
                af[mt][3] = As[base + 8 * LDAB + 4];
            }
            #pragma unroll
            for (int nt = 0; nt < 8; nt++) {
                int base = (wn + nt * 8 + gid) * LDAB + ks + tig;
                bf[nt][0] = Bs[base];
                bf[nt][1] = Bs[base + 4];
            }
            #pragma unroll
            for (int mt = 0; mt < 2; mt++)
                #pragma unroll
                for (int nt = 0; nt < 8; nt++)
                    mma8(acc[mt][nt], af[mt], bf[nt]);
        }
    }

    #pragma unroll
    for (int mt = 0; mt < 2; mt++) {
        #pragma unroll
        for (int nt = 0; nt < 8; nt++) {
            int r0 = m0 + wm + mt * 16 + gid;
            int c0 = coff + n0 + wn + nt * 8 + tig * 2;
            float2 v0 = make_float2(acc[mt][nt][0], acc[mt][nt][1]);
            float2 v1 = make_float2(acc[mt][nt][2], acc[mt][nt][3]);
            *(float2*)&C[(size_t)r0 * ldc + c0] = v0;
            *(float2*)&C[(size_t)(r0 + 8) * ldc + c0] = v1;
        }
    }
}

// ---------------- RMSNorm + RoPE + scatter to [B,H,T,Dh] ----------------------
__global__ __launch_bounds__(128) void qkv_postprocess_kernel(
    const float* __restrict__ qnw, const float* __restrict__ knw)
{
    const int tg = blockIdx.x;
    const int b = tg / TSEQ;
    const int t = tg - b * TSEQ;
    const int hh = blockIdx.y;
    const int d = threadIdx.x;

    const float* src;
    float* dst;
    const float* w = qnw;
    bool rope = true;
    if (hh < NH) {
        src = g_qkv + (size_t)tg * 4096 + hh * DH;
        dst = g_q + ((size_t)(b * NH + hh) * TSEQ + t) * DH;
    } else if (hh < NH + NKV) {
        int h = hh - NH;
        src = g_qkv + (size_t)tg * 4096 + 2048 + h * DH;
        w = knw;
        dst = g_k + ((size_t)(b * NKV + h) * TSEQ + t) * DH;
    } else {
        int h = hh - NH - NKV;
        src = g_qkv + (size_t)tg * 4096 + 3072 + h * DH;
        dst = g_v + ((size_t)(b * NKV + h) * TSEQ + t) * DH;
        rope = false;
    }

    float x = src[d];
    if (!rope) { dst[d] = x; return; }

    float ss = x * x;
    #pragma unroll
    for (int o = 16; o > 0; o >>= 1) ss += __shfl_xor_sync(0xffffffffu, ss, o);
    __shared__ float red[4];
    if ((d & 31) == 0) red[d >> 5] = ss;
    __syncthreads();
    float total = red[0] + red[1] + red[2] + red[3];
    float rms = rsqrtf(total * (1.0f / 128.0f) + 1e-6f);
    float nx = x * rms * w[d];

    __shared__ float sh[128];
    sh[d] = nx;
    __syncthreads();
    float rot = (d < 64) ? -sh[d + 64] : sh[d - 64];
    int i = d & 63;
    float c = g_cos[t * 64 + i];
    float s = g_sin[t * 64 + i];
    dst[d] = nx * c + rot * s;
}

// ---------------- Flash attention (causal, GQA) on mma.sync tf32 --------------
// 64 q-rows x 64 k-rows per tile, 128 threads (4 warps).
// Dyn smem (u32 units): Qs[64*132] | KVs[64*136] | Ps[64*68] | m,l,al [64 each]
#define FQ_OFF  0
#define FKV_OFF 8448
#define FP_OFF  17152
#define FM_OFF  21504
#define FL_OFF  21568
#define FA_OFF  21632
#define FLASH_SMEM_BYTES ((21696) * 4)

__global__ __launch_bounds__(128, 2) void flash_attn_kernel() {
    extern __shared__ uint32_t dsm[];
    uint32_t* Qs  = dsm + FQ_OFF;    // [m][k] pitch 132, tf32 (pre-scaled)
    uint32_t* KVs = dsm + FKV_OFF;   // K: [n][k] pitch 136; later V: [k][n] pitch 136
    uint32_t* Ps  = dsm + FP_OFF;    // [m][k] pitch 68; S fp32 then P tf32
    float* Psf    = (float*)Ps;
    float* m_s  = (float*)(dsm + FM_OFF);
    float* l_s  = (float*)(dsm + FL_OFF);
    float* al_s = (float*)(dsm + FA_OFF);

    const int tid  = threadIdx.x;
    const int lane = tid & 31;
    const int wid  = tid >> 5;
    const int gid  = lane >> 2;
    const int tig  = lane & 3;
    const int wm   = (wid & 1) * 32;
    const int wn   = (wid >> 1) * 32;   // S-phase n offset (32-wide)
    const int wno  = (wid >> 1) * 64;   // PV-phase n offset (64-wide)

    const int bh = blockIdx.y;
    const int b = bh >> 4;
    const int h = bh & 15;
    const int hk = h >> 1;
    const int q0 = blockIdx.x * 64;

    const float* Qg = g_q + ((size_t)(b * NH + h) * TSEQ + q0) * DH;
    const float* Kg = g_k + (size_t)(b * NKV + hk) * TSEQ * DH;
    const float* Vg = g_v + (size_t)(b * NKV + hk) * TSEQ * DH;

    const float scale = 0.08838834764831845f;  // 1/sqrt(128)

    // load Q (scaled, tf32): 64 rows x 128, half-row per thread
    {
        const int r = tid >> 1;
        const int seg = (tid & 1) * 64;
        #pragma unroll
        for (int qq = 0; qq < 16; qq++) {
            float4 v = *(const float4*)(Qg + (size_t)r * DH + seg + qq * 4);
            *(uint4*)&Qs[r * 132 + seg + qq * 4] = cvt4s(v, scale);
        }
    }
    if (tid < 64) { m_s[tid] = -INFINITY; l_s[tid] = 0.f; }

    float acc[2][8][4];   // PV accumulator: rows 32wm+16mt+gid(+8), cols 64wno+8nt+2tig(+1)
    #pragma unroll
    for (int mt = 0; mt < 2; mt++)
        #pragma unroll
        for (int nt = 0; nt < 8; nt++)
            #pragma unroll
            for (int r = 0; r < 4; r++) acc[mt][nt][r] = 0.f;

    __syncthreads();

    for (int k0 = 0; k0 <= q0; k0 += 64) {
        // ---- load K tile: KVs[n][k] pitch 136 ----
        {
            const int r = tid >> 1;
            const int seg = (tid & 1) * 64;
            #pragma unroll
            for (int qq = 0; qq < 16; qq++) {
                float4 v = *(const float4*)(Kg + (size_t)(k0 + r) * DH + seg + qq * 4);
                *(uint4*)&KVs[r * 136 + seg + qq * 4] = cvt4(v);
            }
        }
        __syncthreads();

        // ---- S = Q @ K^T (warp tile 32x32) ----
        float sacc[2][4][4];
        #pragma unroll
        for (int mt = 0; mt < 2; mt++)
            #pragma unroll
            for (int nt = 0; nt < 4; nt++)
                #pragma unroll
                for (int r = 0; r < 4; r++) sacc[mt][nt][r] = 0.f;

        #pragma unroll
        for (int ks = 0; ks < 128; ks += 8) {
            uint32_t af[2][4], bf[4][2];
            #pragma unroll
            for (int mt = 0; mt < 2; mt++) {
                int base = (wm + mt * 16 + gid) * 132 + ks + tig;
                af[mt][0] = Qs[base];
                af[mt][1] = Qs[base + 8 * 132];
                af[mt][2] = Qs[base + 4];
                af[mt][3] = Qs[base + 8 * 132 + 4];
            }
            #pragma unroll
            for (int nt = 0; nt < 4; nt++) {
                int base = (wn + nt * 8 + gid) * 136 + ks + tig;
                bf[nt][0] = KVs[base];
                bf[nt][1] = KVs[base + 4];
            }
            #pragma unroll
            for (int mt = 0; mt < 2; mt++)
                #pragma unroll
                for (int nt = 0; nt < 4; nt++)
                    mma8(sacc[mt][nt], af[mt], bf[nt]);
        }

        // mask (diag tile) + store S (fp32) to Ps
        const bool diag = (k0 == q0);
        #pragma unroll
        for (int mt = 0; mt < 2; mt++) {
            #pragma unroll
            for (int nt = 0; nt < 4; nt++) {
                int r0 = wm + mt * 16 + gid;
                int c0 = wn + nt * 8 + tig * 2;
                float s0 = sacc[mt][nt][0], s1 = sacc[mt][nt][1];
                float s2 = sacc[mt][nt][2], s3 = sacc[mt][nt][3];
                if (diag) {
                    if (c0     > r0)     s0 = -1e30f;
                    if (c0 + 1 > r0)     s1 = -1e30f;
                    if (c0     > r0 + 8) s2 = -1e30f;
                    if (c0 + 1 > r0 + 8) s3 = -1e30f;
                }
                *(float2*)&Psf[r0 * 68 + c0]       = make_float2(s0, s1);
                *(float2*)&Psf[(r0 + 8) * 68 + c0] = make_float2(s2, s3);
            }
        }
        __syncthreads();

        // ---- softmax (threads 0..63) overlapped with V load (threads 64..127) ----
        if (tid < 64) {
            const int r = tid;
            float mo = m_s[r];
            float mx = mo;
            #pragma unroll
            for (int i = 0; i < 16; i++) {
                float4 sv = *(const float4*)&Psf[r * 68 + i * 4];
                mx = fmaxf(mx, fmaxf(fmaxf(sv.x, sv.y), fmaxf(sv.z, sv.w)));
            }
            float al = __expf(mo - mx);
            float lsum = 0.f;
            #pragma unroll
            for (int i = 0; i < 16; i++) {
                float4 sv = *(const float4*)&Psf[r * 68 + i * 4];
                float p0 = __expf(sv.x - mx);
                float p1 = __expf(sv.y - mx);
                float p2 = __expf(sv.z - mx);
                float p3 = __expf(sv.w - mx);
                lsum += (p0 + p1) + (p2 + p3);
                uint4 pu;
                pu.x = f2tf32(p0); pu.y = f2tf32(p1);
                pu.z = f2tf32(p2); pu.w = f2tf32(p3);
                *(uint4*)&Ps[r * 68 + i * 4] = pu;
            }
            m_s[r] = mx;
            l_s[r] = l_s[r] * al + lsum;
            al_s[r] = al;
        } else {
            // V tile: KVs[k][n] pitch 136 (one row per thread)
            const int r = tid - 64;
            #pragma unroll
            for (int qq = 0; qq < 32; qq++) {
                float4 v = *(const float4*)(Vg + (size_t)(k0 + r) * DH + qq * 4);
                *(uint4*)&KVs[r * 136 + qq * 4] = cvt4(v);
            }
        }
        __syncthreads();

        // ---- acc = acc*alpha + P @ V (warp tile 32x64) ----
        #pragma unroll
        for (int mt = 0; mt < 2; mt++) {
            float a0 = al_s[wm + mt * 16 + gid];
            float a1 = al_s[wm + mt * 16 + gid + 8];
            #pragma unroll
            for (int nt = 0; nt < 8; nt++) {
                acc[mt][nt][0] *= a0; acc[mt][nt][1] *= a0;
                acc[mt][nt][2] *= a1; acc[mt][nt][3] *= a1;
            }
        }
        #pragma unroll
        for (int ks = 0; ks < 64; ks += 8) {
            uint32_t af[2][4], bf[8][2];
            #pragma unroll
            for (int mt = 0; mt < 2; mt++) {
                int base = (wm + mt * 16 + gid) * 68 + ks + tig;
                af[mt][0] = Ps[base];
                af[mt][1] = Ps[base + 8 * 68];
                af[mt][2] = Ps[base + 4];
                af[mt][3] = Ps[base + 8 * 68 + 4];
            }
            #pragma unroll
            for (int nt = 0; nt < 8; nt++) {
                int base = (ks + tig) * 136 + wno + nt * 8 + gid;
                bf[nt][0] = KVs[base];
                bf[nt][1] = KVs[base + 4 * 136];
            }
            #pragma unroll
            for (int mt = 0; mt < 2; mt++)
                #pragma unroll
                for (int nt = 0; nt < 8; nt++)
                    mma8(acc[mt][nt], af[mt], bf[nt]);
        }
        __syncthreads();  // protect KVs/Ps before next iteration
    }

    // epilogue: divide by l, write ctx [B,T,H*Dh]
    #pragma unroll
    for (int mt = 0; mt < 2; mt++) {
        int r0 = wm + mt * 16 + gid;
        float inv0 = 1.0f / l_s[r0];
        float inv1 = 1.0f / l_s[r0 + 8];
        #pragma unroll
        for (int nt = 0; nt < 8; nt++) {
            int c0 = wno + nt * 8 + tig * 2;
            float* o0 = g_ctx + (((size_t)b * TSEQ + q0 + r0) * NH + h) * DH + c0;
            float* o1 = g_ctx + (((size_t)b * TSEQ + q0 + r0 + 8) * NH + h) * DH + c0;
            *(float2*)o0 = make_float2(acc[mt][nt][0] * inv0, acc[mt][nt][1] * inv0);
            *(float2*)o1 = make_float2(acc[mt][nt][2] * inv1, acc[mt][nt][3] * inv1);
        }
    }
}

// ---------------- launch ------------------------------------------------------
extern "C" void kernel_launch(void* const* d_in, const int* in_sizes, int n_in,
                              void* d_out, int out_size) {
    const float* x   = (const float*)d_in[0];
    const float* wq  = (const float*)d_in[1];
    const float* wk  = (const float*)d_in[2];
    const float* wv  = (const float*)d_in[3];
    const float* wo  = (const float*)d_in[4];
    const float* qnw = (const float*)d_in[5];
    const float* knw = (const float*)d_in[6];
    float* out = (float*)d_out;

    float *qkv_p, *ctx_p;
    cudaGetSymbolAddress((void**)&qkv_p, g_qkv);
    cudaGetSymbolAddress((void**)&ctx_p, g_ctx);

    build_rope_kernel<<<TSEQ, 64>>>();

    // QKV projections (mma.sync tf32)
    tf32gemm_kernel<<<dim3(16, 32), 256>>>(x, wq, qkv_p, DMODEL, 4096, 0);
    tf32gemm_kernel<<<dim3(8, 32), 256>>>(x, wk, qkv_p, DMODEL, 4096, 2048);
    tf32gemm_kernel<<<dim3(8, 32), 256>>>(x, wv, qkv_p, DMODEL, 4096, 3072);

    qkv_postprocess_kernel<<<dim3(MROWS, NH + 2 * NKV), 128>>>(qnw, knw);

    cudaFuncSetAttribute(flash_attn_kernel,
                         cudaFuncAttributeMaxDynamicSharedMemorySize,
                         FLASH_SMEM_BYTES);
    flash_attn_kernel<<<dim3(TSEQ / 64, BQ * NH), 128, FLASH_SMEM_BYTES>>>();

    // Output projection
    tf32gemm_kernel<<<dim3(16, 32), 256>>>(ctx_p, wo, out, DMODEL, DMODEL, 0);
}

// round 6
// speedup vs baseline: 3.1319x; 1.1856x over previous
#include <cuda_runtime.h>
#include <math.h>
#include <stdint.h>

// Problem constants
#define BQ   2
#define TSEQ 2048
#define DMODEL 2048
#define NH   16
#define NKV  8
#define DH   128
#define MROWS (BQ*TSEQ)   // 4096

// ---------------- device scratch ----------------------------------------------
__device__ float g_qkv[MROWS * 4096];         // q(2048) | k(1024) | v(1024)
__device__ float g_q  [BQ * NH  * TSEQ * DH]; // tf32-rounded, pre-scaled by 1/sqrt(128)
__device__ float g_k  [BQ * NKV * TSEQ * DH]; // tf32-rounded
__device__ float g_v  [BQ * NKV * TSEQ * DH]; // tf32-rounded
__device__ float g_ctx[MROWS * DMODEL];
__device__ float g_cos[TSEQ * 64];
__device__ float g_sin[TSEQ * 64];

// ---------------- helpers -----------------------------------------------------
__device__ __forceinline__ uint32_t f2tf32(float f) {
    uint32_t u;
    asm("cvt.rna.tf32.f32 %0, %1;" : "=r"(u) : "f"(f));
    return u;
}
__device__ __forceinline__ uint32_t smem_u32(const void* p) {
    uint32_t a;
    asm("{ .reg .u64 t; cvta.to.shared.u64 t, %1; cvt.u32.u64 %0, t; }" : "=r"(a) : "l"(p));
    return a;
}
// D += A(m16k8 row) * B(k8n8 col), tf32
__device__ __forceinline__ void mma8(float* d, const uint32_t* a, const uint32_t* b) {
    asm volatile(
        "mma.sync.aligned.m16n8k8.row.col.f32.tf32.tf32.f32 "
        "{%0,%1,%2,%3}, {%4,%5,%6,%7}, {%8,%9}, {%0,%1,%2,%3};"
        : "+f"(d[0]), "+f"(d[1]), "+f"(d[2]), "+f"(d[3])
        : "r"(a[0]), "r"(a[1]), "r"(a[2]), "r"(a[3]), "r"(b[0]), "r"(b[1]));
}
#define CPA16(dst, src) asm volatile("cp.async.cg.shared.global [%0], [%1], 16;" :: "r"(dst), "l"(src) : "memory")
#define CPC()   asm volatile("cp.async.commit_group;" ::: "memory")
#define CPW1()  asm volatile("cp.async.wait_group 1;" ::: "memory")
#define CPW3()  asm volatile("cp.async.wait_group 3;" ::: "memory")

// fast exp on the fma/alu pipes: x <= 0 expected
__device__ __forceinline__ float expf_fast(float x) {
    float z = x * 1.4426950408889634f;
    z = fmaxf(z, -126.0f);
    float r = z + 12582912.0f;                       // round-to-nearest integer
    int   i = __float_as_int(r) - 0x4B400000;
    float f = z - (r - 12582912.0f);                 // f in [-0.5, 0.5]
    float p = fmaf(f, 0.0013333558f, 0.0096181291f); // 2^f poly (deg 5)
    p = fmaf(f, p, 0.0555041087f);
    p = fmaf(f, p, 0.2402265069f);
    p = fmaf(f, p, 0.6931471806f);
    p = fmaf(f, p, 1.0f);
    return __int_as_float(__float_as_int(p) + (i << 23));
}

// ---------------- RoPE table --------------------------------------------------
__global__ void build_rope_kernel() {
    int t = blockIdx.x;
    int i = threadIdx.x;  // 0..63
    double inv = exp(-((double)(2 * i) / 128.0) * log(1.0e6));
    float af = (float)((double)t * inv);
    g_cos[t * 64 + i] = cosf(af);
    g_sin[t * 64 + i] = sinf(af);
}

// ---------------- TF32 GEMM: C[m,n] = A[M,K] @ W[N,K]^T -----------------------
// 256x128 tile, BK=16, 4-stage cp.async, 256 threads (8 warps), warp tile 64x64.
#define GBM 256
#define GBN 128
#define GBK 16
#define GP  20                          // smem pitch (floats)
#define GSTG 4
#define GA_WORDS (GBM * GP)             // 5120
#define GB_WORDS (GBN * GP)             // 2560
#define GSTG_WORDS (GA_WORDS + GB_WORDS)
#define GEMM_SMEM (GSTG * GSTG_WORDS * 4)   // 122880 B

__global__ __launch_bounds__(256, 1) void gemm_kernel(
    const float* __restrict__ A, const float* __restrict__ W0,
    const float* __restrict__ W1, const float* __restrict__ W2,
    int ns1, int ns2, float* __restrict__ C, int ldc)
{
    extern __shared__ float gs[];
    const int tid = threadIdx.x, lane = tid & 31, wid = tid >> 5;
    const int gid = lane >> 2, tig = lane & 3;
    const int wm = (wid & 3) * 64, wn = (wid >> 2) * 64;
    const int m0 = blockIdx.y * GBM;
    const int n0 = blockIdx.x * GBN;
    const int K = DMODEL;

    const float* Bw; int nb;
    if (n0 < ns1)      { Bw = W0; nb = n0; }
    else if (n0 < ns2) { Bw = W1; nb = n0 - ns1; }
    else               { Bw = W2; nb = n0 - ns2; }

    const float* asrc = A  + (size_t)(m0 + tid) * K;                       // whole row
    const float* bsrc = Bw + (size_t)(nb + (tid >> 1)) * K + (tid & 1) * 8; // half row
    const uint32_t smb = smem_u32(gs);
    const uint32_t adst = smb + tid * GP * 4;
    const uint32_t bdst = smb + (GA_WORDS + (tid >> 1) * GP + (tid & 1) * 8) * 4;

    const int niter = K / GBK;  // 128

    #pragma unroll
    for (int s = 0; s < GSTG; s++) {
        const int k0 = s * GBK;
        const uint32_t so = s * GSTG_WORDS * 4;
        #pragma unroll
        for (int c = 0; c < 4; c++) CPA16(adst + so + c * 16, asrc + k0 + c * 4);
        #pragma unroll
        for (int c = 0; c < 2; c++) CPA16(bdst + so + c * 16, bsrc + k0 + c * 4);
        CPC();
    }

    float acc[4][8][4];
    #pragma unroll
    for (int mt = 0; mt < 4; mt++)
        #pragma unroll
        for (int nt = 0; nt < 8; nt++)
            #pragma unroll
            for (int r = 0; r < 4; r++) acc[mt][nt][r] = 0.f;

    for (int kt = 0; kt < niter; kt++) {
        CPW3();
        __syncthreads();
        const float* sa = gs + (kt % GSTG) * GSTG_WORDS;
        const float* sb = sa + GA_WORDS;
        #pragma unroll
        for (int ks = 0; ks < 2; ks++) {
            uint32_t af[4][4], bf[8][2];
            #pragma unroll
            for (int mt = 0; mt < 4; mt++) {
                int base = (wm + mt * 16 + gid) * GP + ks * 8 + tig;
                af[mt][0] = f2tf32(sa[base]);
                af[mt][1] = f2tf32(sa[base + 8 * GP]);
                af[mt][2] = f2tf32(sa[base + 4]);
                af[mt][3] = f2tf32(sa[base + 8 * GP + 4]);
            }
            #pragma unroll
            for (int nt = 0; nt < 8; nt++) {
                int base = (wn + nt * 8 + gid) * GP + ks * 8 + tig;
                bf[nt][0] = f2tf32(sb[base]);
                bf[nt][1] = f2tf32(sb[base + 4]);
            }
            #pragma unroll
            for (int mt = 0; mt < 4; mt++)
                #pragma unroll
                for (int nt = 0; nt < 8; nt++)
                    mma8(acc[mt][nt], af[mt], bf[nt]);
        }
        __syncthreads();
        if (kt + GSTG < niter) {
            const int k0 = (kt + GSTG) * GBK;
            const uint32_t so = (kt % GSTG) * GSTG_WORDS * 4;
            #pragma unroll
            for (int c = 0; c < 4; c++) CPA16(adst + so + c * 16, asrc + k0 + c * 4);
            #pragma unroll
            for (int c = 0; c < 2; c++) CPA16(bdst + so + c * 16, bsrc + k0 + c * 4);
        }
        CPC();
    }

    #pragma unroll
    for (int mt = 0; mt < 4; mt++) {
        #pragma unroll
        for (int nt = 0; nt < 8; nt++) {
            int r0 = m0 + wm + mt * 16 + gid;
            int c0 = n0 + wn + nt * 8 + tig * 2;
            *(float2*)&C[(size_t)r0 * ldc + c0]       = make_float2(acc[mt][nt][0], acc[mt][nt][1]);
            *(float2*)&C[(size_t)(r0 + 8) * ldc + c0] = make_float2(acc[mt][nt][2], acc[mt][nt][3]);
        }
    }
}

// ---------------- RMSNorm + RoPE + scatter (tf32 pre-round, Q pre-scale) ------
__global__ __launch_bounds__(128) void qkv_postprocess_kernel(
    const float* __restrict__ qnw, const float* __restrict__ knw)
{
    const int tg = blockIdx.x;
    const int b = tg / TSEQ;
    const int t = tg - b * TSEQ;
    const int hh = blockIdx.y;
    const int d = threadIdx.x;

    const float* src;
    float* dst;
    const float* w = qnw;
    bool rope = true;
    float outscale = 0.08838834764831845f;   // 1/sqrt(128) folded into Q
    if (hh < NH) {
        src = g_qkv + (size_t)tg * 4096 + hh * DH;
        dst = g_q + ((size_t)(b * NH + hh) * TSEQ + t) * DH;
    } else if (hh < NH + NKV) {
        int h = hh - NH;
        src = g_qkv + (size_t)tg * 4096 + 2048 + h * DH;
        w = knw;
        outscale = 1.0f;
        dst = g_k + ((size_t)(b * NKV + h) * TSEQ + t) * DH;
    } else {
        int h = hh - NH - NKV;
        src = g_qkv + (size_t)tg * 4096 + 3072 + h * DH;
        dst = g_v + ((size_t)(b * NKV + h) * TSEQ + t) * DH;
        rope = false;
    }

    float x = src[d];
    if (!rope) { dst[d] = __uint_as_float(f2tf32(x)); return; }

    float ss = x * x;
    #pragma unroll
    for (int o = 16; o > 0; o >>= 1) ss += __shfl_xor_sync(0xffffffffu, ss, o);
    __shared__ float red[4];
    if ((d & 31) == 0) red[d >> 5] = ss;
    __syncthreads();
    float total = red[0] + red[1] + red[2] + red[3];
    float rms = rsqrtf(total * (1.0f / 128.0f) + 1e-6f);
    float nx = x * rms * w[d];

    __shared__ float sh[128];
    sh[d] = nx;
    __syncthreads();
    float rot = (d < 64) ? -sh[d + 64] : sh[d - 64];
    int i = d & 63;
    float c = g_cos[t * 64 + i];
    float s = g_sin[t * 64 + i];
    dst[d] = __uint_as_float(f2tf32((nx * c + rot * s) * outscale));
}

// ---------------- Flash attention v2 ------------------------------------------
// 64q x 64k tiles, 128 threads (4 warps), warp owns 16 S-rows.
// Register softmax, FFMA exp, cp.async K/V streaming, P kept in registers.
#define FQW (64 * 132)
#define FKW (64 * 132)
#define FVW (64 * 136)
#define FLASH_SMEM ((FQW + FKW + FVW) * 4)   // 102400 B

__global__ __launch_bounds__(128, 2) void flash_attn_kernel() {
    extern __shared__ float fsm[];
    float* Qs = fsm;
    float* Ks = fsm + FQW;
    const uint32_t* Qu = (const uint32_t*)Qs;
    const uint32_t* Ku = (const uint32_t*)Ks;
    const uint32_t* Vu = (const uint32_t*)(fsm + FQW + FKW);

    const int tid  = threadIdx.x;
    const int lane = tid & 31;
    const int wid  = tid >> 5;
    const int gid  = lane >> 2;
    const int tig  = lane & 3;
    const int wm   = wid * 16;          // warp's S-row base

    const int bh = blockIdx.y;
    const int b = bh >> 4;
    const int h = bh & 15;
    const int hk = h >> 1;
    const int q0 = (31 - blockIdx.x) * 64;     // big blocks first
    const int ntiles = (q0 >> 6) + 1;

    const float* Qg = g_q + ((size_t)(b * NH + h) * TSEQ + q0) * DH;
    const float* Kg = g_k + (size_t)(b * NKV + hk) * TSEQ * DH;
    const float* Vg = g_v + (size_t)(b * NKV + hk) * TSEQ * DH;

    // cp.async geometry: thread -> row tid>>1, half (tid&1)*64 floats (16 chunks)
    const int cr = tid >> 1;
    const int ch = (tid & 1) * 64;
    const uint32_t smb = smem_u32(fsm);
    const uint32_t qdst = smb + (cr * 132 + ch) * 4;
    const uint32_t kdst = smb + (FQW + cr * 132 + ch) * 4;
    const uint32_t vdst = smb + (FQW + FKW + cr * 136 + ch) * 4;
    const float* qsrc = Qg + (size_t)cr * DH + ch;
    const float* ksrc = Kg + (size_t)cr * DH + ch;
    const float* vsrc = Vg + (size_t)cr * DH + ch;

    // prologue: group A_{-1} = Q + K[0], group B_{-1} = V[0]
    #pragma unroll
    for (int c = 0; c < 16; c++) CPA16(qdst + c * 16, qsrc + c * 4);
    #pragma unroll
    for (int c = 0; c < 16; c++) CPA16(kdst + c * 16, ksrc + c * 4);
    CPC();
    #pragma unroll
    for (int c = 0; c < 16; c++) CPA16(vdst + c * 16, vsrc + c * 4);
    CPC();

    float acc[16][4];
    #pragma unroll
    for (int nt = 0; nt < 16; nt++)
        #pragma unroll
        for (int r = 0; r < 4; r++) acc[nt][r] = 0.f;
    float m0r = -INFINITY, m1r = -INFINITY, l0r = 0.f, l1r = 0.f;

    for (int j = 0; j < ntiles; j++) {
        const int k0 = j * 64;
        CPW1();                 // K[j] (and Q) resident
        __syncthreads();

        // ---- S = Q @ K^T, warp tile 16x64 ----
        float sacc[8][4];
        #pragma unroll
        for (int nt = 0; nt < 8; nt++)
            #pragma unroll
            for (int r = 0; r < 4; r++) sacc[nt][r] = 0.f;

        #pragma unroll
        for (int ks = 0; ks < 16; ks++) {
            uint32_t af[4], bf[8][2];
            int ab = (wm + gid) * 132 + ks * 8 + tig;
            af[0] = Qu[ab];
            af[1] = Qu[ab + 8 * 132];
            af[2] = Qu[ab + 4];
            af[3] = Qu[ab + 8 * 132 + 4];
            #pragma unroll
            for (int nt = 0; nt < 8; nt++) {
                int bb = (nt * 8 + gid) * 132 + ks * 8 + tig;
                bf[nt][0] = Ku[bb];
                bf[nt][1] = Ku[bb + 4];
            }
            #pragma unroll
            for (int nt = 0; nt < 8; nt++) mma8(sacc[nt], af, bf[nt]);
        }
        __syncthreads();        // all warps done with Ks

        // issue K[j+1] (group A_j)
        if (j + 1 < ntiles) {
            const float* ks2 = ksrc + (size_t)(k0 + 64) * DH;
            #pragma unroll
            for (int c = 0; c < 16; c++) CPA16(kdst + c * 16, ks2 + c * 4);
        }
        CPC();

        // ---- mask + online softmax in registers ----
        const int r0 = wm + gid, r1 = r0 + 8;   // local rows
        if (k0 == q0) {
            #pragma unroll
            for (int nt = 0; nt < 8; nt++) {
                int c0 = nt * 8 + tig * 2;
                if (c0     > r0) sacc[nt][0] = -1e30f;
                if (c0 + 1 > r0) sacc[nt][1] = -1e30f;
                if (c0     > r1) sacc[nt][2] = -1e30f;
                if (c0 + 1 > r1) sacc[nt][3] = -1e30f;
            }
        }
        float mx0 = m0r, mx1 = m1r;
        #pragma unroll
        for (int nt = 0; nt < 8; nt++) {
            mx0 = fmaxf(mx0, fmaxf(sacc[nt][0], sacc[nt][1]));
            mx1 = fmaxf(mx1, fmaxf(sacc[nt][2], sacc[nt][3]));
        }
        mx0 = fmaxf(mx0, __shfl_xor_sync(0xffffffffu, mx0, 1));
        mx0 = fmaxf(mx0, __shfl_xor_sync(0xffffffffu, mx0, 2));
        mx1 = fmaxf(mx1, __shfl_xor_sync(0xffffffffu, mx1, 1));
        mx1 = fmaxf(mx1, __shfl_xor_sync(0xffffffffu, mx1, 2));
        float a0 = expf_fast(m0r - mx0);
        float a1 = expf_fast(m1r - mx1);
        m0r = mx0; m1r = mx1;

        float s0 = 0.f, s1 = 0.f;
        #pragma unroll
        for (int nt = 0; nt < 8; nt++) {
            float p0 = __uint_as_float(f2tf32(expf_fast(sacc[nt][0] - mx0)));
            float p1 = __uint_as_float(f2tf32(expf_fast(sacc[nt][1] - mx0)));
            float p2 = __uint_as_float(f2tf32(expf_fast(sacc[nt][2] - mx1)));
            float p3 = __uint_as_float(f2tf32(expf_fast(sacc[nt][3] - mx1)));
            s0 += p0 + p1; s1 += p2 + p3;
            sacc[nt][0] = p0; sacc[nt][1] = p1; sacc[nt][2] = p2; sacc[nt][3] = p3;
        }
        s0 += __shfl_xor_sync(0xffffffffu, s0, 1);
        s0 += __shfl_xor_sync(0xffffffffu, s0, 2);
        s1 += __shfl_xor_sync(0xffffffffu, s1, 1);
        s1 += __shfl_xor_sync(0xffffffffu, s1, 2);
        l0r = l0r * a0 + s0;
        l1r = l1r * a1 + s1;
        #pragma unroll
        for (int nt = 0; nt < 16; nt++) {
            acc[nt][0] *= a0; acc[nt][1] *= a0;
            acc[nt][2] *= a1; acc[nt][3] *= a1;
        }

        // ---- wait V[j] (group B_{j-1}), then PV ----
        CPW1();
        __syncthreads();

        const int lq = lane & ~3;
        const int lsrc0 = lq | (tig >> 1);
        const int lsrc2 = lq | (2 + (tig >> 1));
        const bool odd = tig & 1;
        #pragma unroll
        for (int kb = 0; kb < 8; kb++) {
            uint32_t c0 = __float_as_uint(sacc[kb][0]);
            uint32_t c1 = __float_as_uint(sacc[kb][1]);
            uint32_t c2 = __float_as_uint(sacc[kb][2]);
            uint32_t c3 = __float_as_uint(sacc[kb][3]);
            uint32_t a[4];
            uint32_t v00 = __shfl_sync(0xffffffffu, c0, lsrc0);
            uint32_t v01 = __shfl_sync(0xffffffffu, c1, lsrc0);
            uint32_t v10 = __shfl_sync(0xffffffffu, c2, lsrc0);
            uint32_t v11 = __shfl_sync(0xffffffffu, c3, lsrc0);
            uint32_t v20 = __shfl_sync(0xffffffffu, c0, lsrc2);
            uint32_t v21 = __shfl_sync(0xffffffffu, c1, lsrc2);
            uint32_t v30 = __shfl_sync(0xffffffffu, c2, lsrc2);
            uint32_t v31 = __shfl_sync(0xffffffffu, c3, lsrc2);
            a[0] = odd ? v01 : v00;
            a[1] = odd ? v11 : v10;
            a[2] = odd ? v21 : v20;
            a[3] = odd ? v31 : v30;
            #pragma unroll
            for (int nt = 0; nt < 16; nt++) {
                uint32_t bfr[2];
                int vb = (kb * 8 + tig) * 136 + nt * 8 + gid;
                bfr[0] = Vu[vb];
                bfr[1] = Vu[vb + 4 * 136];
                mma8(acc[nt], a, bfr);
            }
        }
        __syncthreads();        // all warps done with Vs

        // issue V[j+1] (group B_j)
        if (j + 1 < ntiles) {
            const float* vs2 = vsrc + (size_t)(k0 + 64) * DH;
            #pragma unroll
            for (int c = 0; c < 16; c++) CPA16(vdst + c * 16, vs2 + c * 4);
        }
        CPC();
    }

    // epilogue
    const float inv0 = 1.0f / l0r;
    const float inv1 = 1.0f / l1r;
    const int gr0 = q0 + wm + gid;
    const int gr1 = gr0 + 8;
    #pragma unroll
    for (int nt = 0; nt < 16; nt++) {
        int c0 = nt * 8 + tig * 2;
        float* o0 = g_ctx + (((size_t)b * TSEQ + gr0) * NH + h) * DH + c0;
        float* o1 = g_ctx + (((size_t)b * TSEQ + gr1) * NH + h) * DH + c0;
        *(float2*)o0 = make_float2(acc[nt][0] * inv0, acc[nt][1] * inv0);
        *(float2*)o1 = make_float2(acc[nt][2] * inv1, acc[nt][3] * inv1);
    }
}

// ---------------- launch ------------------------------------------------------
extern "C" void kernel_launch(void* const* d_in, const int* in_sizes, int n_in,
                              void* d_out, int out_size) {
    const float* x   = (const float*)d_in[0];
    const float* wq  = (const float*)d_in[1];
    const float* wk  = (const float*)d_in[2];
    const float* wv  = (const float*)d_in[3];
    const float* wo  = (const float*)d_in[4];
    const float* qnw = (const float*)d_in[5];
    const float* knw = (const float*)d_in[6];
    float* out = (float*)d_out;

    float *qkv_p, *ctx_p;
    cudaGetSymbolAddress((void**)&qkv_p, g_qkv);
    cudaGetSymbolAddress((void**)&ctx_p, g_ctx);

    build_rope_kernel<<<TSEQ, 64>>>();

    cudaFuncSetAttribute(gemm_kernel,
                         cudaFuncAttributeMaxDynamicSharedMemorySize, GEMM_SMEM);

    // merged QKV projection: N = 4096 (q 2048 | k 1024 | v 1024)
    gemm_kernel<<<dim3(32, 16), 256, GEMM_SMEM>>>(x, wq, wk, wv, 2048, 3072,
                                                  qkv_p, 4096);

    qkv_postprocess_kernel<<<dim3(MROWS, NH + 2 * NKV), 128>>>(qnw, knw);

    cudaFuncSetAttribute(flash_attn_kernel,
                         cudaFuncAttributeMaxDynamicSharedMemorySize, FLASH_SMEM);
    flash_attn_kernel<<<dim3(TSEQ / 64, BQ * NH), 128, FLASH_SMEM>>>();

    // output projection
    gemm_kernel<<<dim3(16, 16), 256, GEMM_SMEM>>>(ctx_p, wo, wo, wo,
                                                  1 << 30, 1 << 30, out, DMODEL);
}